// round 14
// baseline (speedup 1.0000x reference)
#include <cuda_runtime.h>
#include <cuda_fp16.h>
#include <cstdint>

// Problem constants
#define B_ 4
#define S_ 2048
#define D_ 1024

// Scratch (device globals: allocation-free per harness rules)
__device__ __half g_qh [B_ * S_ * D_];            // 16 MB  q in fp16
__device__ __half g_WT [2 * D_ * D_];             // 4 MB   [WqT ; WvT] as [2048,1024]
__device__ __half g_QKV[(size_t)B_ * S_ * 2 * D_];// 32 MB  [8192, 2048]: WQ | WKV
__device__ __half g_scores[(size_t)B_ * S_ * S_]; // 32 MB  scores -> attn in place

// ---------------------------------------------------------------------------
// Helpers
// ---------------------------------------------------------------------------
__device__ __forceinline__ uint32_t smem_u32(const void* p) {
    uint32_t a;
    asm("{ .reg .u64 t; cvta.to.shared.u64 t, %1; cvt.u32.u64 %0, t; }" : "=r"(a) : "l"(p));
    return a;
}

__device__ __forceinline__ void mma_f16(float* c, const uint32_t* a, const uint32_t* b) {
    asm volatile(
        "mma.sync.aligned.m16n8k16.row.col.f32.f16.f16.f32 "
        "{%0,%1,%2,%3}, {%4,%5,%6,%7}, {%8,%9}, {%0,%1,%2,%3};"
        : "+f"(c[0]), "+f"(c[1]), "+f"(c[2]), "+f"(c[3])
        : "r"(a[0]), "r"(a[1]), "r"(a[2]), "r"(a[3]),
          "r"(b[0]), "r"(b[1]));
}

#define LDMX4(r0, r1, r2, r3, addr) \
    asm volatile("ldmatrix.sync.aligned.m8n8.x4.shared.b16 {%0,%1,%2,%3}, [%4];" \
        : "=r"(r0), "=r"(r1), "=r"(r2), "=r"(r3) : "r"(addr))

#define LDMX4T(r0, r1, r2, r3, addr) \
    asm volatile("ldmatrix.sync.aligned.m8n8.x4.trans.shared.b16 {%0,%1,%2,%3}, [%4];" \
        : "=r"(r0), "=r"(r1), "=r"(r2), "=r"(r3) : "r"(addr))

#define CP_ASYNC16(dst_u32, src_ptr) \
    asm volatile("cp.async.cg.shared.global [%0], [%1], 16;" \
        :: "r"(dst_u32), "l"(src_ptr) : "memory")
#define CP_COMMIT() asm volatile("cp.async.commit_group;" ::: "memory")
#define CP_WAIT1()  asm volatile("cp.async.wait_group 1;"  ::: "memory")

// ---------------------------------------------------------------------------
// FP16 pipelined GEMM (R8/R13 champion structure): C = scale * A[M,K] @ B',
// fp32 accumulate.
//   TRANSB_LDM = false: B given as [N,K] (k-contiguous rows), ldmatrix normal.
//   TRANSB_LDM = true : B given as [K,N] (n-contiguous rows), ldmatrix.trans,
//                       256B smem rows with XOR-16B swizzle.
// CTA tile 128x128, 4 warps (64x64 warp tile), KC=64, 3-stage cp.async ring,
// register double-buffered fragments + cross-chunk fragment prefetch inside
// the ks==3 slot (issue_stage BEFORE the wait), 2 CTAs/SM.
// CAUSAL: skip tiles with bn > bm. LIMITK: K truncated at (bm+1)*128.
// OUT_HALF: write __half (intermediates) else float (final output).
// ---------------------------------------------------------------------------
#define BM 128
#define BN 128
#define KC 64
#define A_STAGE (BM * 128)            // 16 KB
#define B_STAGE (BN * 128)            // 16 KB
#define B_OFF   (3 * A_STAGE)         // 49152
#define SMEM_TOTAL (3 * (A_STAGE + B_STAGE))  // 98304

template <bool CAUSAL, bool LIMITK, bool OUT_HALF, bool TRANSB_LDM>
__global__ void __launch_bounds__(128, 2)
gemm_h(const __half* __restrict__ A, const __half* __restrict__ Bn,
       void* __restrict__ Cv,
       int K, int lda, int ldb, int ldc, float scale,
       size_t aBatch, size_t bBatch, size_t cBatch)
{
    const int bm = blockIdx.y;
    const int bn = blockIdx.x;
    if (CAUSAL && bn > bm) return;   // whole CTA exits, no barriers yet

    extern __shared__ __align__(128) char smem[];
    const uint32_t sbase = smem_u32(smem);

    const int tid  = threadIdx.x;
    const int warp = tid >> 5;
    const int lane = tid & 31;
    const int wm = (warp >> 1) * 64;   // 2 warp-rows of 64
    const int wn = (warp & 1) * 64;    // 2 warp-cols of 64
    const int g  = lane >> 2;
    const int tq = lane & 3;

    const __half* Ab = A + aBatch * blockIdx.z + (size_t)(bm * BM) * lda;
    const __half* Bb = Bn + bBatch * blockIdx.z +
                       (TRANSB_LDM ? (size_t)(bn * BN) : (size_t)(bn * BN) * ldb);

    const int kEnd = LIMITK ? min(K, (bm + 1) * BM) : K;
    const int nc = kEnd / KC;

    float acc[4][8][4] = {};

    // ---- stage loader: 16B granules, swizzled dst, one commit per stage ----
    auto issue_stage = [&](int c) {
        if (c < nc) {
            const int s = c % 3;
            const int k0 = c * KC;
            const uint32_t da = sbase + s * A_STAGE;
            const uint32_t db = sbase + B_OFF + s * B_STAGE;
            #pragma unroll
            for (int i = 0; i < 8; i++) {           // A: 1024 granules, 128B rows
                const int gid = tid + i * 128;
                const int row = gid >> 3, ch = gid & 7;
                CP_ASYNC16(da + row * 128 + ((ch ^ (row & 7)) << 4),
                           Ab + (size_t)row * lda + k0 + ch * 8);
            }
            if (TRANSB_LDM) {
                // B tile: KC=64 k-rows x 128 n-cols, 256B rows, 16 chunks/row
                #pragma unroll
                for (int i = 0; i < 8; i++) {
                    const int gid = tid + i * 128;
                    const int row = gid >> 4, ch = gid & 15;
                    const uint32_t dst = db + row * 256 + ((ch & 8) << 4) +
                                         (((ch & 7) ^ (row & 7)) << 4);
                    CP_ASYNC16(dst, Bb + (size_t)(k0 + row) * ldb + ch * 8);
                }
            } else {
                // B tile: 128 n-rows x KC k, 128B rows
                #pragma unroll
                for (int i = 0; i < 8; i++) {
                    const int gid = tid + i * 128;
                    const int row = gid >> 3, ch = gid & 7;
                    CP_ASYNC16(db + row * 128 + ((ch ^ (row & 7)) << 4),
                               Bb + (size_t)row * ldb + k0 + ch * 8);
                }
            }
        }
        CP_COMMIT();
    };

    // per-lane ldmatrix address invariants
    const int l15  = lane & 15;
    const int lhi  = lane >> 4;          // A: k half select
    const int sx   = lane & 7;           // swizzle xor (128B rows)
    const int bkb  = (lane >> 3) & 1;    // B non-trans: k half select
    const int bRowOfs = ((lane >> 4) << 3) + (lane & 7);  // B non-trans row
    const int tRow = lane & 15;          // B trans: k row 0..15
    const int tCh  = lane >> 4;          // B trans: +0/+1 16B chunk

    uint32_t af[2][4][4];
    uint32_t bf[2][8][2];

    // fragment loader for one k16 step of the stage starting at aSB/bSB
    auto load_frags = [&](uint32_t aSB, uint32_t bSB, int ks, int bu) {
        const uint32_t aRow = aSB + (wm + l15) * 128;
        #pragma unroll
        for (int mi = 0; mi < 4; mi++) {
            const uint32_t addr = aRow + mi * (16 * 128) + (((2 * ks + lhi) ^ sx) << 4);
            LDMX4(af[bu][mi][0], af[bu][mi][1], af[bu][mi][2], af[bu][mi][3], addr);
        }
        if (TRANSB_LDM) {
            const int krow = 16 * ks + tRow;
            const uint32_t rBase = bSB + krow * 256;
            #pragma unroll
            for (int q = 0; q < 4; q++) {
                const int ch = (wn >> 3) + 2 * q + tCh;   // 16B chunk (n index /8)
                const uint32_t addr = rBase + ((ch & 8) << 4) +
                                      (((ch & 7) ^ (tRow & 7)) << 4);
                LDMX4T(bf[bu][2 * q][0], bf[bu][2 * q][1],
                       bf[bu][2 * q + 1][0], bf[bu][2 * q + 1][1], addr);
            }
        } else {
            const uint32_t bRow = bSB + (wn + bRowOfs) * 128;
            #pragma unroll
            for (int nq = 0; nq < 4; nq++) {
                const uint32_t addr = bRow + nq * (16 * 128) + (((2 * ks + bkb) ^ sx) << 4);
                LDMX4(bf[bu][2 * nq][0], bf[bu][2 * nq][1],
                      bf[bu][2 * nq + 1][0], bf[bu][2 * nq + 1][1], addr);
            }
        }
    };

    // ---- preamble: stages 0,1 in flight; frags(chunk0, ks0) resident ----
    issue_stage(0);
    issue_stage(1);
    CP_WAIT1();            // stage 0 complete (stage 1 may be pending)
    __syncthreads();

    uint32_t aSB = sbase, bSB = sbase + B_OFF;
    load_frags(aSB, bSB, 0, 0);

    for (int c = 0; c < nc; c++) {
        #pragma unroll
        for (int ks = 0; ks < 4; ks++) {
            const int bu = ks & 1;
            if (ks < 3) {
                load_frags(aSB, bSB, ks + 1, bu ^ 1);
            } else if (c + 1 < nc) {
                // boundary (champion order): refill ring, THEN wait+sync,
                // then prefetch next chunk's ks0 frags into the other buffer.
                issue_stage(c + 2);
                CP_WAIT1();        // stage c+1 complete (c+2 is the 1 in flight)
                __syncthreads();   // publish all threads' stage c+1 data
                const int sn = (c + 1) % 3;
                aSB = sbase + sn * A_STAGE;
                bSB = sbase + B_OFF + sn * B_STAGE;
                load_frags(aSB, bSB, 0, bu ^ 1);
            }
            #pragma unroll
            for (int mi = 0; mi < 4; mi++)
                #pragma unroll
                for (int ni = 0; ni < 8; ni++)
                    mma_f16(acc[mi][ni], af[bu][mi], bf[bu][ni]);
        }
    }

    // ---- epilogue ----
    #pragma unroll
    for (int mi = 0; mi < 4; mi++) {
        #pragma unroll
        for (int ni = 0; ni < 8; ni++) {
            const int row0 = bm * BM + wm + mi * 16 + g;
            const int col  = bn * BN + wn + ni * 8 + tq * 2;
            const float v0 = acc[mi][ni][0] * scale, v1 = acc[mi][ni][1] * scale;
            const float v2 = acc[mi][ni][2] * scale, v3 = acc[mi][ni][3] * scale;
            if (OUT_HALF) {
                __half* Cb = (__half*)Cv + cBatch * blockIdx.z;
                *reinterpret_cast<__half2*>(&Cb[(size_t)row0 * ldc + col]) =
                    __floats2half2_rn(v0, v1);
                *reinterpret_cast<__half2*>(&Cb[(size_t)(row0 + 8) * ldc + col]) =
                    __floats2half2_rn(v2, v3);
            } else {
                float* Cb = (float*)Cv + cBatch * blockIdx.z;
                *reinterpret_cast<float2*>(&Cb[(size_t)row0 * ldc + col]) = make_float2(v0, v1);
                *reinterpret_cast<float2*>(&Cb[(size_t)(row0 + 8) * ldc + col]) = make_float2(v2, v3);
            }
        }
    }
}

// ---------------------------------------------------------------------------
// Merged prepass (one launch): blocks [0, COPY_BLKS) copy q fp32->fp16
// (float4 granules); remaining blocks transpose Wq/Wv fp32 -> fp16 into WT.
// ---------------------------------------------------------------------------
#define COPY_BLKS (B_ * S_ * D_ / 4 / 256)         // 8192
#define TR_BLKS_PER_W ((D_ / 32) * (D_ / 32))      // 1024

__global__ void __launch_bounds__(256) prepass(const float4* __restrict__ q4,
                                               uint2* __restrict__ qh,
                                               const float* __restrict__ Wq,
                                               const float* __restrict__ Wv,
                                               __half* __restrict__ WT)
{
    const int bid = blockIdx.x;
    const int tid = threadIdx.x;

    if (bid < COPY_BLKS) {
        const int i = bid * 256 + tid;
        const float4 v = q4[i];
        const __half2 h0 = __floats2half2_rn(v.x, v.y);
        const __half2 h1 = __floats2half2_rn(v.z, v.w);
        uint2 u;
        u.x = *reinterpret_cast<const uint32_t*>(&h0);
        u.y = *reinterpret_cast<const uint32_t*>(&h1);
        qh[i] = u;
        return;
    }

    __shared__ float t[32][33];
    const int r  = bid - COPY_BLKS;
    const int zz = r / TR_BLKS_PER_W;                 // 0: Wq, 1: Wv
    const int rr = r - zz * TR_BLKS_PER_W;
    const int bx = rr & (D_ / 32 - 1);
    const int by = rr >> 5;
    const float* src = zz ? Wv : Wq;
    __half* d = WT + (size_t)zz * D_ * D_;

    const int tx = tid & 31;
    const int ty = tid >> 5;                          // 0..7
    int x = bx * 32 + tx;
    int y = by * 32 + ty;
    #pragma unroll
    for (int j = 0; j < 32; j += 8)
        t[ty + j][tx] = src[(size_t)(y + j) * D_ + x];
    __syncthreads();
    x = by * 32 + tx;
    y = bx * 32 + ty;
    #pragma unroll
    for (int j = 0; j < 32; j += 8)
        d[(size_t)(y + j) * D_ + x] = __float2half_rn(t[tx][ty + j]);
}

// ---------------------------------------------------------------------------
// Causal row softmax (fp16 in/out, fp32 math), register-cached single pass.
// Compute is PREDICATED on valid pairs (p < np): masked lanes previously
// computed exp(-3.4e38 - m) = 0, so skipping them and writing literal zeros
// in [np, tileEnd) is bit-identical while halving dynamic instructions.
// ---------------------------------------------------------------------------
__global__ void __launch_bounds__(128) softmax_h(__half* __restrict__ scores)
{
    __shared__ float red[4];
    __shared__ float bcast;

    const int q = blockIdx.x;
    __half2* row = reinterpret_cast<__half2*>(
        scores + ((size_t)blockIdx.y * S_ + q) * S_);
    const int len = q + 1;
    const int np  = (len + 1) >> 1;     // half2 pairs containing valid data
    const int tid = threadIdx.x;

    float vx[8], vy[8];

    // read + max (valid pairs only)
    float m = -3.4e38f;
    #pragma unroll
    for (int i = 0; i < 8; i++) {
        const int p = tid + (i << 7);
        if (p < np) {
            const float2 f = __half22float2(row[p]);
            vx[i] = f.x;
            vy[i] = (2 * p + 1 < len) ? f.y : -3.4e38f;
            m = fmaxf(m, fmaxf(vx[i], vy[i]));
        }
    }
    #pragma unroll
    for (int o = 16; o; o >>= 1) m = fmaxf(m, __shfl_xor_sync(0xffffffffu, m, o));
    if ((tid & 31) == 0) red[tid >> 5] = m;
    __syncthreads();
    m = fmaxf(fmaxf(red[0], red[1]), fmaxf(red[2], red[3]));

    // exp + sum (valid pairs only; masked .y already -huge -> exp = 0)
    float s = 0.f;
    #pragma unroll
    for (int i = 0; i < 8; i++) {
        const int p = tid + (i << 7);
        if (p < np) {
            vx[i] = __expf(vx[i] - m);
            vy[i] = __expf(vy[i] - m);
            s += vx[i] + vy[i];
        }
    }
    #pragma unroll
    for (int o = 16; o; o >>= 1) s += __shfl_xor_sync(0xffffffffu, s, o);
    __syncthreads();
    if ((tid & 31) == 0) red[tid >> 5] = s;
    __syncthreads();
    if (tid == 0) bcast = 1.f / (red[0] + red[1] + red[2] + red[3]);
    __syncthreads();
    const float inv = bcast;

    // write: normalized attn on valid pairs; literal zeros to 128-boundary
    const int tEnd2 = (((q >> 7) + 1) << 7) >> 1;  // pairs to write
    #pragma unroll
    for (int i = 0; i < 8; i++) {
        const int p = tid + (i << 7);
        if (p < np) {
            row[p] = __floats2half2_rn(vx[i] * inv, vy[i] * inv);
        } else if (p < tEnd2) {
            row[p] = __floats2half2_rn(0.f, 0.f);
        }
    }
}

// ---------------------------------------------------------------------------
// Launch
// ---------------------------------------------------------------------------
extern "C" void kernel_launch(void* const* d_in, const int* in_sizes, int n_in,
                              void* d_out, int out_size)
{
    (void)in_sizes; (void)n_in; (void)out_size;
    const float* q  = (const float*)d_in[0];
    const float* Wq = (const float*)d_in[1];
    // d_in[2] = Wk (unused by reference), d_in[4] = mask (causal, analytic)
    const float* Wv = (const float*)d_in[3];
    float* out = (float*)d_out;

    __half *pq, *pWT, *pQKV, *pS;
    cudaGetSymbolAddress((void**)&pq,   g_qh);
    cudaGetSymbolAddress((void**)&pWT,  g_WT);
    cudaGetSymbolAddress((void**)&pQKV, g_QKV);
    cudaGetSymbolAddress((void**)&pS,   g_scores);

    cudaFuncSetAttribute(gemm_h<false, false, true, false>,
                         cudaFuncAttributeMaxDynamicSharedMemorySize, SMEM_TOTAL);
    cudaFuncSetAttribute(gemm_h<true, false, true, false>,
                         cudaFuncAttributeMaxDynamicSharedMemorySize, SMEM_TOTAL);
    cudaFuncSetAttribute(gemm_h<false, true, false, true>,
                         cudaFuncAttributeMaxDynamicSharedMemorySize, SMEM_TOTAL);

    // 0) Merged prepass: q -> half; Wq+Wv transposed -> [2048,1024] fp16
    prepass<<<COPY_BLKS + 2 * TR_BLKS_PER_W, 256>>>(
        (const float4*)q, (uint2*)pq, Wq, Wv, pWT);

    // 1) Fused projections: QKV[8192,2048] = q @ [Wq | Wv]  (B = [2048,1024])
    {
        const dim3 grid(2 * D_ / BN, (B_ * S_) / BM, 1);
        gemm_h<false, false, true, false><<<grid, 128, SMEM_TOTAL>>>(
            pq, pWT, pQKV, D_, D_, D_, 2 * D_, 1.0f, 0, 0, 0);
    }

    // 2) Scores = WQ @ WKV^T / 32, causal tiles only (fp16 out)
    {
        const dim3 grid(S_ / BN, S_ / BM, B_);
        gemm_h<true, false, true, false><<<grid, 128, SMEM_TOTAL>>>(
            pQKV, pQKV + D_, pS, D_, 2 * D_, 2 * D_, S_, 1.0f / 32.0f,
            (size_t)S_ * 2 * D_, (size_t)S_ * 2 * D_, (size_t)S_ * S_);
    }

    // 3) Causal softmax in place (fp16, register-cached, compute-predicated)
    softmax_h<<<dim3(S_, B_), 128>>>(pS);

    // 4) out = attn @ WKV: B consumed directly as [K=S, N=D] via ldmatrix.trans;
    //    K truncated causally; fp32 out.
    {
        const dim3 grid(D_ / BN, S_ / BM, B_);
        gemm_h<false, true, false, true><<<grid, 128, SMEM_TOTAL>>>(
            pS, pQKV + D_, out, S_, S_, 2 * D_, D_, 1.0f,
            (size_t)S_ * S_, (size_t)S_ * 2 * D_, (size_t)S_ * D_);
    }
}

// round 15
// speedup vs baseline: 1.0154x; 1.0154x over previous
#include <cuda_runtime.h>
#include <cuda_fp16.h>
#include <cstdint>

// Problem constants
#define B_ 4
#define S_ 2048
#define D_ 1024

// Scratch (device globals: allocation-free per harness rules)
__device__ __half g_qh [B_ * S_ * D_];            // 16 MB  q in fp16
__device__ __half g_WT [2 * D_ * D_];             // 4 MB   [WqT ; WvT] as [2048,1024]
__device__ __half g_QKV[(size_t)B_ * S_ * 2 * D_];// 32 MB  [8192, 2048]: WQ | WKV
__device__ __half g_scores[(size_t)B_ * S_ * S_]; // 32 MB  scores -> attn in place

// ---------------------------------------------------------------------------
// Helpers
// ---------------------------------------------------------------------------
__device__ __forceinline__ uint32_t smem_u32(const void* p) {
    uint32_t a;
    asm("{ .reg .u64 t; cvta.to.shared.u64 t, %1; cvt.u32.u64 %0, t; }" : "=r"(a) : "l"(p));
    return a;
}

__device__ __forceinline__ void mma_f16(float* c, const uint32_t* a, const uint32_t* b) {
    asm volatile(
        "mma.sync.aligned.m16n8k16.row.col.f32.f16.f16.f32 "
        "{%0,%1,%2,%3}, {%4,%5,%6,%7}, {%8,%9}, {%0,%1,%2,%3};"
        : "+f"(c[0]), "+f"(c[1]), "+f"(c[2]), "+f"(c[3])
        : "r"(a[0]), "r"(a[1]), "r"(a[2]), "r"(a[3]),
          "r"(b[0]), "r"(b[1]));
}

#define LDMX4(r0, r1, r2, r3, addr) \
    asm volatile("ldmatrix.sync.aligned.m8n8.x4.shared.b16 {%0,%1,%2,%3}, [%4];" \
        : "=r"(r0), "=r"(r1), "=r"(r2), "=r"(r3) : "r"(addr))

#define LDMX4T(r0, r1, r2, r3, addr) \
    asm volatile("ldmatrix.sync.aligned.m8n8.x4.trans.shared.b16 {%0,%1,%2,%3}, [%4];" \
        : "=r"(r0), "=r"(r1), "=r"(r2), "=r"(r3) : "r"(addr))

#define CP_ASYNC16(dst_u32, src_ptr) \
    asm volatile("cp.async.cg.shared.global [%0], [%1], 16;" \
        :: "r"(dst_u32), "l"(src_ptr) : "memory")
#define CP_COMMIT() asm volatile("cp.async.commit_group;" ::: "memory")
#define CP_WAIT1()  asm volatile("cp.async.wait_group 1;"  ::: "memory")

// ---------------------------------------------------------------------------
// FP16 pipelined GEMM (R8/R13 champion structure): C = scale * A[M,K] @ B',
// fp32 accumulate.
//   TRANSB_LDM = false: B given as [N,K] (k-contiguous rows), ldmatrix normal.
//   TRANSB_LDM = true : B given as [K,N] (n-contiguous rows), ldmatrix.trans,
//                       256B smem rows with XOR-16B swizzle.
// CTA tile 128x128, 4 warps (64x64 warp tile), KC=64, 3-stage cp.async ring,
// register double-buffered fragments + cross-chunk fragment prefetch inside
// the ks==3 slot (issue_stage BEFORE the wait), 2 CTAs/SM.
// CAUSAL: skip tiles with bn > bm. LIMITK: K truncated at (bm+1)*128.
// OUT_HALF: write __half (intermediates) else float (final output).
// ---------------------------------------------------------------------------
#define BM 128
#define BN 128
#define KC 64
#define A_STAGE (BM * 128)            // 16 KB
#define B_STAGE (BN * 128)            // 16 KB
#define B_OFF   (3 * A_STAGE)         // 49152
#define SMEM_TOTAL (3 * (A_STAGE + B_STAGE))  // 98304

template <bool CAUSAL, bool LIMITK, bool OUT_HALF, bool TRANSB_LDM>
__global__ void __launch_bounds__(128, 2)
gemm_h(const __half* __restrict__ A, const __half* __restrict__ Bn,
       void* __restrict__ Cv,
       int K, int lda, int ldb, int ldc, float scale,
       size_t aBatch, size_t bBatch, size_t cBatch)
{
    const int bm = blockIdx.y;
    const int bn = blockIdx.x;
    if (CAUSAL && bn > bm) return;   // whole CTA exits, no barriers yet

    extern __shared__ __align__(128) char smem[];
    const uint32_t sbase = smem_u32(smem);

    const int tid  = threadIdx.x;
    const int warp = tid >> 5;
    const int lane = tid & 31;
    const int wm = (warp >> 1) * 64;   // 2 warp-rows of 64
    const int wn = (warp & 1) * 64;    // 2 warp-cols of 64
    const int g  = lane >> 2;
    const int tq = lane & 3;

    const __half* Ab = A + aBatch * blockIdx.z + (size_t)(bm * BM) * lda;
    const __half* Bb = Bn + bBatch * blockIdx.z +
                       (TRANSB_LDM ? (size_t)(bn * BN) : (size_t)(bn * BN) * ldb);

    const int kEnd = LIMITK ? min(K, (bm + 1) * BM) : K;
    const int nc = kEnd / KC;

    float acc[4][8][4] = {};

    // ---- stage loader: 16B granules, swizzled dst, one commit per stage ----
    auto issue_stage = [&](int c) {
        if (c < nc) {
            const int s = c % 3;
            const int k0 = c * KC;
            const uint32_t da = sbase + s * A_STAGE;
            const uint32_t db = sbase + B_OFF + s * B_STAGE;
            #pragma unroll
            for (int i = 0; i < 8; i++) {           // A: 1024 granules, 128B rows
                const int gid = tid + i * 128;
                const int row = gid >> 3, ch = gid & 7;
                CP_ASYNC16(da + row * 128 + ((ch ^ (row & 7)) << 4),
                           Ab + (size_t)row * lda + k0 + ch * 8);
            }
            if (TRANSB_LDM) {
                // B tile: KC=64 k-rows x 128 n-cols, 256B rows, 16 chunks/row
                #pragma unroll
                for (int i = 0; i < 8; i++) {
                    const int gid = tid + i * 128;
                    const int row = gid >> 4, ch = gid & 15;
                    const uint32_t dst = db + row * 256 + ((ch & 8) << 4) +
                                         (((ch & 7) ^ (row & 7)) << 4);
                    CP_ASYNC16(dst, Bb + (size_t)(k0 + row) * ldb + ch * 8);
                }
            } else {
                // B tile: 128 n-rows x KC k, 128B rows
                #pragma unroll
                for (int i = 0; i < 8; i++) {
                    const int gid = tid + i * 128;
                    const int row = gid >> 3, ch = gid & 7;
                    CP_ASYNC16(db + row * 128 + ((ch ^ (row & 7)) << 4),
                               Bb + (size_t)row * ldb + k0 + ch * 8);
                }
            }
        }
        CP_COMMIT();
    };

    // per-lane ldmatrix address invariants
    const int l15  = lane & 15;
    const int lhi  = lane >> 4;          // A: k half select
    const int sx   = lane & 7;           // swizzle xor (128B rows)
    const int bkb  = (lane >> 3) & 1;    // B non-trans: k half select
    const int bRowOfs = ((lane >> 4) << 3) + (lane & 7);  // B non-trans row
    const int tRow = lane & 15;          // B trans: k row 0..15
    const int tCh  = lane >> 4;          // B trans: +0/+1 16B chunk

    uint32_t af[2][4][4];
    uint32_t bf[2][8][2];

    // fragment loader for one k16 step of the stage starting at aSB/bSB
    auto load_frags = [&](uint32_t aSB, uint32_t bSB, int ks, int bu) {
        const uint32_t aRow = aSB + (wm + l15) * 128;
        #pragma unroll
        for (int mi = 0; mi < 4; mi++) {
            const uint32_t addr = aRow + mi * (16 * 128) + (((2 * ks + lhi) ^ sx) << 4);
            LDMX4(af[bu][mi][0], af[bu][mi][1], af[bu][mi][2], af[bu][mi][3], addr);
        }
        if (TRANSB_LDM) {
            const int krow = 16 * ks + tRow;
            const uint32_t rBase = bSB + krow * 256;
            #pragma unroll
            for (int q = 0; q < 4; q++) {
                const int ch = (wn >> 3) + 2 * q + tCh;   // 16B chunk (n index /8)
                const uint32_t addr = rBase + ((ch & 8) << 4) +
                                      (((ch & 7) ^ (tRow & 7)) << 4);
                LDMX4T(bf[bu][2 * q][0], bf[bu][2 * q][1],
                       bf[bu][2 * q + 1][0], bf[bu][2 * q + 1][1], addr);
            }
        } else {
            const uint32_t bRow = bSB + (wn + bRowOfs) * 128;
            #pragma unroll
            for (int nq = 0; nq < 4; nq++) {
                const uint32_t addr = bRow + nq * (16 * 128) + (((2 * ks + bkb) ^ sx) << 4);
                LDMX4(bf[bu][2 * nq][0], bf[bu][2 * nq][1],
                      bf[bu][2 * nq + 1][0], bf[bu][2 * nq + 1][1], addr);
            }
        }
    };

    // ---- preamble: stages 0,1 in flight; frags(chunk0, ks0) resident ----
    issue_stage(0);
    issue_stage(1);
    CP_WAIT1();            // stage 0 complete (stage 1 may be pending)
    __syncthreads();

    uint32_t aSB = sbase, bSB = sbase + B_OFF;
    load_frags(aSB, bSB, 0, 0);

    for (int c = 0; c < nc; c++) {
        #pragma unroll
        for (int ks = 0; ks < 4; ks++) {
            const int bu = ks & 1;
            if (ks < 3) {
                load_frags(aSB, bSB, ks + 1, bu ^ 1);
            } else if (c + 1 < nc) {
                // boundary (champion order): refill ring, THEN wait+sync,
                // then prefetch next chunk's ks0 frags into the other buffer.
                issue_stage(c + 2);
                CP_WAIT1();        // stage c+1 complete (c+2 is the 1 in flight)
                __syncthreads();   // publish all threads' stage c+1 data
                const int sn = (c + 1) % 3;
                aSB = sbase + sn * A_STAGE;
                bSB = sbase + B_OFF + sn * B_STAGE;
                load_frags(aSB, bSB, 0, bu ^ 1);
            }
            #pragma unroll
            for (int mi = 0; mi < 4; mi++)
                #pragma unroll
                for (int ni = 0; ni < 8; ni++)
                    mma_f16(acc[mi][ni], af[bu][mi], bf[bu][ni]);
        }
    }

    // ---- epilogue ----
    #pragma unroll
    for (int mi = 0; mi < 4; mi++) {
        #pragma unroll
        for (int ni = 0; ni < 8; ni++) {
            const int row0 = bm * BM + wm + mi * 16 + g;
            const int col  = bn * BN + wn + ni * 8 + tq * 2;
            const float v0 = acc[mi][ni][0] * scale, v1 = acc[mi][ni][1] * scale;
            const float v2 = acc[mi][ni][2] * scale, v3 = acc[mi][ni][3] * scale;
            if (OUT_HALF) {
                __half* Cb = (__half*)Cv + cBatch * blockIdx.z;
                *reinterpret_cast<__half2*>(&Cb[(size_t)row0 * ldc + col]) =
                    __floats2half2_rn(v0, v1);
                *reinterpret_cast<__half2*>(&Cb[(size_t)(row0 + 8) * ldc + col]) =
                    __floats2half2_rn(v2, v3);
            } else {
                float* Cb = (float*)Cv + cBatch * blockIdx.z;
                *reinterpret_cast<float2*>(&Cb[(size_t)row0 * ldc + col]) = make_float2(v0, v1);
                *reinterpret_cast<float2*>(&Cb[(size_t)(row0 + 8) * ldc + col]) = make_float2(v2, v3);
            }
        }
    }
}

// ---------------------------------------------------------------------------
// Merged prepass (one launch): blocks [0, COPY_BLKS) copy q fp32->fp16
// (float4 granules); remaining blocks transpose Wq/Wv fp32 -> fp16 into WT.
// ---------------------------------------------------------------------------
#define COPY_BLKS (B_ * S_ * D_ / 4 / 256)         // 8192
#define TR_BLKS_PER_W ((D_ / 32) * (D_ / 32))      // 1024

__global__ void __launch_bounds__(256) prepass(const float4* __restrict__ q4,
                                               uint2* __restrict__ qh,
                                               const float* __restrict__ Wq,
                                               const float* __restrict__ Wv,
                                               __half* __restrict__ WT)
{
    const int bid = blockIdx.x;
    const int tid = threadIdx.x;

    if (bid < COPY_BLKS) {
        const int i = bid * 256 + tid;
        const float4 v = q4[i];
        const __half2 h0 = __floats2half2_rn(v.x, v.y);
        const __half2 h1 = __floats2half2_rn(v.z, v.w);
        uint2 u;
        u.x = *reinterpret_cast<const uint32_t*>(&h0);
        u.y = *reinterpret_cast<const uint32_t*>(&h1);
        qh[i] = u;
        return;
    }

    __shared__ float t[32][33];
    const int r  = bid - COPY_BLKS;
    const int zz = r / TR_BLKS_PER_W;                 // 0: Wq, 1: Wv
    const int rr = r - zz * TR_BLKS_PER_W;
    const int bx = rr & (D_ / 32 - 1);
    const int by = rr >> 5;
    const float* src = zz ? Wv : Wq;
    __half* d = WT + (size_t)zz * D_ * D_;

    const int tx = tid & 31;
    const int ty = tid >> 5;                          // 0..7
    int x = bx * 32 + tx;
    int y = by * 32 + ty;
    #pragma unroll
    for (int j = 0; j < 32; j += 8)
        t[ty + j][tx] = src[(size_t)(y + j) * D_ + x];
    __syncthreads();
    x = by * 32 + tx;
    y = bx * 32 + ty;
    #pragma unroll
    for (int j = 0; j < 32; j += 8)
        d[(size_t)(y + j) * D_ + x] = __float2half_rn(t[tx][ty + j]);
}

// ---------------------------------------------------------------------------
// Causal row softmax (fp16 in/out, fp32 math). R13 compute philosophy
// (straight-line exp on all 16 slots, guards on memory only) with uint4
// vectorized I/O: 2 LDG.128 + 2 STG.128 per thread instead of 8+8 32-bit ops.
// Group (= 16B = 8 halves) guards are warp-uniform; element masking to -inf
// is branch-free selects. Values written are identical to R13's.
// ---------------------------------------------------------------------------
__global__ void __launch_bounds__(128) softmax_h(__half* __restrict__ scores)
{
    __shared__ float red[4];
    __shared__ float bcast;

    const int q = blockIdx.x;
    uint4* row = reinterpret_cast<uint4*>(
        scores + ((size_t)blockIdx.y * S_ + q) * S_);
    const int len  = q + 1;
    const int gEnd = ((q >> 7) + 1) << 4;   // tileEnd / 8 groups of 8 halves
    const int tid  = threadIdx.x;

    float v[2][8];

    // ---- vectorized read + element mask (scores in [len, tileEnd) are
    //      finite GEMM outputs; masked to -inf so exp gives exact 0) ----
    #pragma unroll
    for (int i = 0; i < 2; i++) {
        const int j = tid + (i << 7);       // group index
        if (j < gEnd) {
            uint4 u = row[j];
            const __half2* h = reinterpret_cast<const __half2*>(&u);
            #pragma unroll
            for (int e = 0; e < 4; e++) {
                const float2 f = __half22float2(h[e]);
                const int base = 8 * j + 2 * e;
                v[i][2 * e]     = (base     < len) ? f.x : -3.4e38f;
                v[i][2 * e + 1] = (base + 1 < len) ? f.y : -3.4e38f;
            }
        } else {
            #pragma unroll
            for (int e = 0; e < 8; e++) v[i][e] = -3.4e38f;
        }
    }

    // ---- max ----
    float m = -3.4e38f;
    #pragma unroll
    for (int i = 0; i < 2; i++)
        #pragma unroll
        for (int e = 0; e < 8; e++) m = fmaxf(m, v[i][e]);
    #pragma unroll
    for (int o = 16; o; o >>= 1) m = fmaxf(m, __shfl_xor_sync(0xffffffffu, m, o));
    if ((tid & 31) == 0) red[tid >> 5] = m;
    __syncthreads();
    m = fmaxf(fmaxf(red[0], red[1]), fmaxf(red[2], red[3]));

    // ---- exp + sum, straight-line on all 16 slots (masked -> exactly 0) ----
    float s = 0.f;
    #pragma unroll
    for (int i = 0; i < 2; i++)
        #pragma unroll
        for (int e = 0; e < 8; e++) {
            v[i][e] = __expf(v[i][e] - m);
            s += v[i][e];
        }
    #pragma unroll
    for (int o = 16; o; o >>= 1) s += __shfl_xor_sync(0xffffffffu, s, o);
    __syncthreads();
    if ((tid & 31) == 0) red[tid >> 5] = s;
    __syncthreads();
    if (tid == 0) bcast = 1.f / (red[0] + red[1] + red[2] + red[3]);
    __syncthreads();
    const float inv = bcast;

    // ---- vectorized write (normalized attn; masked slots are 0) ----
    #pragma unroll
    for (int i = 0; i < 2; i++) {
        const int j = tid + (i << 7);
        if (j < gEnd) {
            uint4 u;
            __half2* h = reinterpret_cast<__half2*>(&u);
            #pragma unroll
            for (int e = 0; e < 4; e++)
                h[e] = __floats2half2_rn(v[i][2 * e] * inv, v[i][2 * e + 1] * inv);
            row[j] = u;
        }
    }
}

// ---------------------------------------------------------------------------
// Launch
// ---------------------------------------------------------------------------
extern "C" void kernel_launch(void* const* d_in, const int* in_sizes, int n_in,
                              void* d_out, int out_size)
{
    (void)in_sizes; (void)n_in; (void)out_size;
    const float* q  = (const float*)d_in[0];
    const float* Wq = (const float*)d_in[1];
    // d_in[2] = Wk (unused by reference), d_in[4] = mask (causal, analytic)
    const float* Wv = (const float*)d_in[3];
    float* out = (float*)d_out;

    __half *pq, *pWT, *pQKV, *pS;
    cudaGetSymbolAddress((void**)&pq,   g_qh);
    cudaGetSymbolAddress((void**)&pWT,  g_WT);
    cudaGetSymbolAddress((void**)&pQKV, g_QKV);
    cudaGetSymbolAddress((void**)&pS,   g_scores);

    cudaFuncSetAttribute(gemm_h<false, false, true, false>,
                         cudaFuncAttributeMaxDynamicSharedMemorySize, SMEM_TOTAL);
    cudaFuncSetAttribute(gemm_h<true, false, true, false>,
                         cudaFuncAttributeMaxDynamicSharedMemorySize, SMEM_TOTAL);
    cudaFuncSetAttribute(gemm_h<false, true, false, true>,
                         cudaFuncAttributeMaxDynamicSharedMemorySize, SMEM_TOTAL);

    // 0) Merged prepass: q -> half; Wq+Wv transposed -> [2048,1024] fp16
    prepass<<<COPY_BLKS + 2 * TR_BLKS_PER_W, 256>>>(
        (const float4*)q, (uint2*)pq, Wq, Wv, pWT);

    // 1) Fused projections: QKV[8192,2048] = q @ [Wq | Wv]  (B = [2048,1024])
    {
        const dim3 grid(2 * D_ / BN, (B_ * S_) / BM, 1);
        gemm_h<false, false, true, false><<<grid, 128, SMEM_TOTAL>>>(
            pq, pWT, pQKV, D_, D_, D_, 2 * D_, 1.0f, 0, 0, 0);
    }

    // 2) Scores = WQ @ WKV^T / 32, causal tiles only (fp16 out)
    {
        const dim3 grid(S_ / BN, S_ / BM, B_);
        gemm_h<true, false, true, false><<<grid, 128, SMEM_TOTAL>>>(
            pQKV, pQKV + D_, pS, D_, 2 * D_, 2 * D_, S_, 1.0f / 32.0f,
            (size_t)S_ * 2 * D_, (size_t)S_ * 2 * D_, (size_t)S_ * S_);
    }

    // 3) Causal softmax in place (fp16, register-cached, uint4 I/O)
    softmax_h<<<dim3(S_, B_), 128>>>(pS);

    // 4) out = attn @ WKV: B consumed directly as [K=S, N=D] via ldmatrix.trans;
    //    K truncated causally; fp32 out.
    {
        const dim3 grid(D_ / BN, S_ / BM, B_);
        gemm_h<false, true, false, true><<<grid, 128, SMEM_TOTAL>>>(
            pS, pQKV + D_, out, S_, S_, 2 * D_, D_, 1.0f,
            (size_t)S_ * S_, (size_t)S_ * 2 * D_, (size_t)S_ * D_);
    }
}